// round 15
// baseline (speedup 1.0000x reference)
#include <cuda_runtime.h>
#include <cstdint>
#include <cstddef>

// Problem constants
#define BATCH   64
#define CPB     3072           // anchors*H*W per batch (3*32*32)
#define CELLS   (BATCH*CPB)    // 196608
#define KSEL    100
#define NPAIR   (BATCH*KSEL)   // 6400
#define PCHUNK  320            // preds per IoU chunk (20 chunks)
#define NIOUB   50             // iou x-blocks (128 targets each)
#define NJB     25             // jloss blocks
#define TKT     512            // select threads
#define NKB     (CELLS/256)    // 768 key-builder blocks
#define NBUK    128            // quarter-octave b-buckets over [2^-32, 1)

// ---------------- scratch (device globals; no allocation) ----------------
__device__ float4 g_p4[NPAIR];        // selected pred corners
__device__ float  g_pa[NPAIR];        // pred areas
__device__ float4 g_t4[NPAIR];        // fixed target corners
__device__ float  g_topv[NPAIR];      // selected confidences
__device__ int    g_miou[NPAIR];      // max IoU per target (float bits, >=0)
__device__ float  g_diou[NPAIR];
__device__ unsigned int g_keys[CELLS];// order-preserving conf keys
__device__ float  g_negp[NKB];        // negpen partials
__device__ float  g_sl1p[NIOUB];      // smooth-l1 partials
__device__ float  g_sl1tot;           // reduced sl1 (already scaled)
__device__ float  g_jp[NJB];          // per-block j-loss partials
__device__ float  g_bm[NBUK];         // compacted bucket centers
__device__ float  g_bs[NBUK*5];       // compacted bucket power sums S0..S4
__device__ int    g_nb;               // number of occupied buckets
__device__ int    g_ctr, g_ctr2;      // last-block counters (self-resetting)

// ---------------- helpers ----------------
__device__ __forceinline__ float rcp_approx(float x) {
    float y; asm("rcp.approx.f32 %0, %1;" : "=f"(y) : "f"(x)); return y;
}
__device__ __forceinline__ float sqrt_approx(float x) {
    float y; asm("sqrt.approx.f32 %0, %1;" : "=f"(y) : "f"(x)); return y;
}
__device__ __forceinline__ float sigmoidf_(float x) {
    return 1.0f / (1.0f + expf(-x));
}

// full-block float sum, result valid in thread 0 (NW warps)
template<int NW>
__device__ __forceinline__ float block_sum(float v) {
    __shared__ float sh[NW];
    #pragma unroll
    for (int o = 16; o > 0; o >>= 1) v += __shfl_down_sync(0xffffffffu, v, o);
    int lane = threadIdx.x & 31, wid = threadIdx.x >> 5;
    if (lane == 0) sh[wid] = v;
    __syncthreads();
    float s = 0.0f;
    if (wid == 0) {
        s = (lane < NW) ? sh[lane] : 0.0f;
        #pragma unroll
        for (int o = NW / 2; o > 0; o >>= 1) s += __shfl_down_sync(0xffffffffu, s, o);
    }
    __syncthreads();   // safe smem reuse by later calls
    return s;
}

// ---------------- kernels ----------------

// Full-chip streaming pass: order-preserving conf keys + negpen partials.
// Blocks < 25 also fix targets + init miou.
__global__ void k_keys(const float* __restrict__ pred, const float* __restrict__ tgt) {
    __shared__ float4 buf[320];
    int blk = blockIdx.x, tid = threadIdx.x;
    const float4* src = (const float4*)pred + (size_t)blk * 320;
    #pragma unroll 2
    for (int i = tid; i < 320; i += 256) buf[i] = src[i];
    __syncthreads();
    const float* f = (const float*)buf;
    float pw = f[tid * 5 + 2], ph = f[tid * 5 + 3], cl = f[tid * 5 + 4];
    float neg = fmaxf(1.0f - pw, 0.0f) + fmaxf(1.0f - ph, 0.0f);
    unsigned int u = __float_as_uint(cl);
    u = (u & 0x80000000u) ? ~u : (u | 0x80000000u);   // order-preserving
    g_keys[blk * 256 + tid] = u;
    float tot = block_sum<8>(neg);
    if (tid == 0) g_negp[blk] = tot;

    if (blk < 25) {   // fused target fix + miou init (j < 6400)
        int j = blk * 256 + tid;
        g_miou[j] = 0;
        const float* t = tgt + (size_t)j * 4;
        float a = t[0], b = t[1], c = t[2], d = t[3];
        float x1 = fminf(a, c), x2 = fmaxf(a, c);
        float y1 = fminf(b, d), y2 = fmaxf(b, d);
        if (x1 == x2) x2 = x1 + 1.0f;
        if (y1 == y2) y2 = y1 + 1.0f;
        g_t4[j] = make_float4(x1, y1, x2, y2);
    }
}

// Per-batch top-100 on L2-hot keys: 12-bit radix-select + hybrid bitonic;
// exact jax ordering (ties -> smaller idx).
__global__ void __launch_bounds__(TKT) k_select(const float* __restrict__ pred) {
    __shared__ unsigned int keys[CPB];          // 12KB
    __shared__ unsigned int hist[4096];         // 16KB
    __shared__ unsigned long long cand[512];    // 4KB
    __shared__ unsigned int tsum[256];
    __shared__ unsigned int safter[256];
    __shared__ unsigned int wsum[8];
    __shared__ unsigned int s_cnt, s_pivot;

    int b = blockIdx.x;
    int tid = threadIdx.x;
    int lane = tid & 31, wid = tid >> 5;

    for (int i = tid; i < 4096; i += TKT) hist[i] = 0;
    if (tid == 0) s_cnt = 0;
    __syncthreads();

    const unsigned int* gk = g_keys + (size_t)b * CPB;
    #pragma unroll
    for (int s = tid; s < CPB; s += TKT) {
        unsigned int u = gk[s];
        keys[s] = u;
        atomicAdd(&hist[u >> 20], 1u);
    }
    __syncthreads();

    // parallel suffix scan over 4096 buckets (16/thread, 256 threads)
    unsigned int sv = 0;
    if (tid < 256) {
        unsigned int s0 = 0;
        #pragma unroll
        for (int q = 0; q < 16; q++) s0 += hist[tid * 16 + q];
        tsum[tid] = s0;
        sv = s0;
        #pragma unroll
        for (int o = 1; o < 32; o <<= 1) {
            unsigned int t = __shfl_down_sync(0xffffffffu, sv, o);
            if (lane + o < 32) sv += t;           // in-warp inclusive suffix
        }
        if (lane == 0) wsum[wid] = sv;
    }
    __syncthreads();
    if (tid < 256) {
        unsigned int hi = 0;
        #pragma unroll
        for (int w = 0; w < 8; w++) if (w > wid) hi += wsum[w];
        safter[tid] = sv + hi - tsum[tid];        // exclusive suffix
        unsigned int run = safter[tid];
        for (int q = 15; q >= 0; q--) {
            unsigned int c = hist[tid * 16 + q];
            run += c;
            if (run >= KSEL && (run - c) < KSEL) s_pivot = tid * 16 + q;
        }
    }
    __syncthreads();
    unsigned int piv = s_pivot;

    // gather candidates (buckets >= pivot)
    #pragma unroll
    for (int s = tid; s < CPB; s += TKT) {
        unsigned int u = keys[s];
        if ((u >> 20) >= piv) {
            unsigned int pos = atomicAdd(&s_cnt, 1u);
            if (pos < 512)
                cand[pos] = ((unsigned long long)u << 32) |
                            (unsigned long long)(0xFFFFFFFFu - (unsigned int)s);
        }
    }
    __syncthreads();
    unsigned int cnt = s_cnt; if (cnt > 512) cnt = 512;
    if (tid >= (int)cnt) cand[tid] = 0ull;
    __syncthreads();

    // hybrid bitonic sort (descending), 1 elem/thread
    unsigned long long v = cand[tid];
    #pragma unroll
    for (unsigned int k = 2; k <= 32; k <<= 1) {
        #pragma unroll
        for (unsigned int j = k >> 1; j > 0; j >>= 1) {
            unsigned long long t = __shfl_xor_sync(0xffffffffu, v, j);
            bool keep_max = (((tid & j) == 0) == ((tid & k) == 0));
            v = (keep_max == (v > t)) ? v : t;
        }
    }
    #pragma unroll
    for (unsigned int k = 64; k <= 512; k <<= 1) {
        for (unsigned int j = k >> 1; j >= 32; j >>= 1) {
            cand[tid] = v;
            __syncthreads();
            unsigned long long t = cand[tid ^ j];
            bool keep_max = (((tid & j) == 0) == ((tid & k) == 0));
            v = (keep_max == (v > t)) ? v : t;
            __syncthreads();
        }
        #pragma unroll
        for (unsigned int j = 16; j > 0; j >>= 1) {
            unsigned long long t = __shfl_xor_sync(0xffffffffu, v, j);
            bool keep_max = (((tid & j) == 0) == ((tid & k) == 0));
            v = (keep_max == (v > t)) ? v : t;
        }
    }
    cand[tid] = v;
    __syncthreads();

    // winners -> postprocessed pred corners
    if (tid < KSEL) {
        unsigned long long m = cand[tid];
        int idx = (int)(0xFFFFFFFFu - (unsigned int)(m & 0xFFFFFFFFull));
        int j = b * KSEL + tid;
        const float* p = pred + (size_t)b * CPB * 5 + (size_t)idx * 5;
        float x = (sigmoidf_(p[0]) + (float)(idx & 31)) * 32.0f;         // + cx, *STRIDE
        float y = (sigmoidf_(p[1]) + (float)((idx >> 5) & 31)) * 32.0f;  // + cy
        float hw = expf(p[2]) * 32.0f * 0.5f;
        float hh = expf(p[3]) * 32.0f * 0.5f;
        float x1 = x - hw, y1 = y - hh, x2 = x + hw, y2 = y + hh;
        g_p4[j] = make_float4(x1, y1, x2, y2);
        g_pa[j] = (x2 - x1) * (y2 - y1);
        g_topv[j] = sigmoidf_(p[4]);
    }
}

// One block: bucket b_i = (1-topv_i)^2 into quarter-octave log buckets;
// per bucket power sums S0..S4 of t = b - m (8 warp-private copies),
// then compact occupied buckets (thread 0, deterministic order).
__global__ void k_stats() {
    __shared__ float ws[8][NBUK * 5];   // 20KB warp-private power sums
    int tid = threadIdx.x;
    int wid = tid >> 5;

    for (int i = tid; i < 8 * NBUK * 5; i += 256) ((float*)ws)[i] = 0.0f;
    __syncthreads();

    #pragma unroll 5
    for (int r = 0; r < 25; r++) {
        float y = g_topv[tid + r * 256];
        float b = (1.0f - y) * (1.0f - y);
        b = fminf(fmaxf(b, 2.3283064e-10f /*2^-32*/), 0.999f);
        int k = (int)floorf(4.0f * __log2f(b)) + 128;
        k = max(0, min(NBUK - 1, k));
        float m = exp2f(0.25f * ((float)k + 0.5f) - 32.0f);  // geometric center
        float t = b - m;
        float* w = ws[wid] + k * 5;
        float t2 = t * t;
        atomicAdd(w + 0, 1.0f);
        atomicAdd(w + 1, t);
        atomicAdd(w + 2, t2);
        atomicAdd(w + 3, t2 * t);
        atomicAdd(w + 4, t2 * t2);
    }
    __syncthreads();

    // reduce 8 warp copies into copy 0
    for (int i = tid; i < NBUK * 5; i += 256) {
        float s = 0.0f;
        #pragma unroll
        for (int w = 0; w < 8; w++) s += ws[w][i];
        ws[0][i] = s;
    }
    __syncthreads();

    if (tid == 0) {                     // deterministic compaction
        int n = 0;
        for (int k = 0; k < NBUK; k++) {
            float S0 = ws[0][k * 5];
            if (S0 > 0.0f) {
                g_bm[n] = exp2f(0.25f * ((float)k + 0.5f) - 32.0f);
                #pragma unroll
                for (int p = 0; p < 5; p++) g_bs[n * 5 + p] = ws[0][k * 5 + p];
                n++;
            }
        }
        g_nb = n;
    }
}

// max IoU over all preds per target (division-free monotone q trick).
// 1000 blocks (50 x 20). blockIdx.y==0 also does DIoU + smooth-L1; the
// last sl1 block folds the 50 partials into g_sl1tot.
__global__ void k_ioumax() {
    __shared__ float4 sp[PCHUNK];
    __shared__ float  sa[PCHUNK];
    int tid = threadIdx.x;
    int pbase = blockIdx.y * PCHUNK;
    for (int p = tid; p < PCHUNK; p += 128) {
        sp[p] = g_p4[pbase + p];
        sa[p] = g_pa[pbase + p];
    }
    __syncthreads();

    int t = blockIdx.x * 128 + tid;
    float4 T = g_t4[t];
    float ta = (T.z - T.x) * (T.w - T.y);
    float qb = 0.0f;
    #pragma unroll 4
    for (int p = 0; p < PCHUNK; p++) {
        float4 P = sp[p];            // broadcast LDS.128
        float ix1 = fmaxf(P.x, T.x);
        float iy1 = fmaxf(P.y, T.y);
        float ix2 = fminf(P.z, T.z);
        float iy2 = fminf(P.w, T.w);
        float w = fmaxf(ix2 - ix1, 0.0f);
        float h = fmaxf(iy2 - iy1, 0.0f);
        float inter = w * h;
        float s = sa[p] + ta;
        float q = inter * rcp_approx(s);
        qb = fmaxf(qb, q);
    }
    float iou = qb / (1.0f - qb);    // q in [0, 0.5] -> safe
    atomicMax(&g_miou[t], __float_as_int(iou));  // bits compare OK: iou >= 0

    if (blockIdx.y == 0) {
        float4 P = g_p4[t];
        float pa = fmaxf(P.z - P.x, 0.0f) * fmaxf(P.w - P.y, 0.0f);
        float tta = fmaxf(T.z - T.x, 0.0f) * fmaxf(T.w - T.y, 0.0f);
        float ix1 = fmaxf(P.x, T.x), iy1 = fmaxf(P.y, T.y);
        float ix2 = fminf(P.z, T.z), iy2 = fminf(P.w, T.w);
        float inter = fmaxf(ix2 - ix1, 0.0f) * fmaxf(iy2 - iy1, 0.0f);
        float iou2 = inter / (pa + tta - inter + 1e-7f);
        float dx = (P.x + P.z) * 0.5f - (T.x + T.z) * 0.5f;
        float dy = (P.y + P.w) * 0.5f - (T.y + T.w) * 0.5f;
        float cd = dx * dx + dy * dy;
        float gx = fmaxf(P.z, T.z) - fminf(P.x, T.x);
        float gy = fmaxf(P.w, T.w) - fminf(P.y, T.y);
        float diag = gx * gx + gy * gy;
        g_diou[t] = 1.0f - (iou2 - cd / (diag + 1e-7f));
        float c0 = P.x - T.x, c1 = P.y - T.y, c2 = P.z - T.z, c3 = P.w - T.w;
        float a0 = fabsf(c0), a1 = fabsf(c1), a2 = fabsf(c2), a3 = fabsf(c3);
        float sl = 0.0f;
        sl += (a0 < 1.0f) ? 0.5f * c0 * c0 : (a0 - 0.5f);
        sl += (a1 < 1.0f) ? 0.5f * c1 * c1 : (a1 - 0.5f);
        sl += (a2 < 1.0f) ? 0.5f * c2 * c2 : (a2 - 0.5f);
        sl += (a3 < 1.0f) ? 0.5f * c3 * c3 : (a3 - 0.5f);
        float tot = block_sum<4>(sl);
        if (tid == 0) {
            g_sl1p[blockIdx.x] = tot;
            __threadfence();
            int c = atomicAdd(&g_ctr2, 1);
            if (c == NIOUB - 1) {               // last sl1 block reduces
                float s = 0.0f;
                #pragma unroll 10
                for (int k2 = 0; k2 < NIOUB; k2++) s += g_sl1p[k2];
                g_sl1tot = s * (1.0f / (25600.0f * 512.0f));  // /(N*4)/DESIRED_SIZE
                g_ctr2 = 0;                     // reset for next replay
            }
        }
    }
}

// Per-j bucketed series: for each occupied b-bucket, order-4 expansion of
// sum_i sqrt(v + t_i) around v = {a,c} + m_k. |t|/(c+m) <= 0.0905 by
// construction -> always convergent, no guard, no fallback.
__global__ void __launch_bounds__(256) k_jloss(float* __restrict__ out) {
    __shared__ float sm[NBUK * 6];       // m, S0..S4 per occupied bucket
    __shared__ int   s_nb;
    __shared__ bool  s_last;
    int tid = threadIdx.x;
    if (tid == 0) s_nb = g_nb;
    __syncthreads();
    int nb = s_nb;
    for (int i = tid; i < nb; i += 256) {
        sm[i * 6 + 0] = g_bm[i];
        #pragma unroll
        for (int p = 0; p < 5; p++) sm[i * 6 + 1 + p] = g_bs[i * 5 + p];
    }
    __syncthreads();

    float sl1 = g_sl1tot;
    int j = blockIdx.x * 256 + tid;
    float mi = fmaxf(__int_as_float(g_miou[j]), 0.0f);
    float x = 2.0f * (1.0f - mi) + g_diou[j] + sl1;
    float a = x * x;
    float xm = 3.5f - x;
    float cc = xm * xm;

    float acc = 0.0f;
    for (int e = 0; e < nb; e++) {
        float m  = sm[e * 6 + 0];        // smem broadcast
        float S0 = sm[e * 6 + 1], S1 = sm[e * 6 + 2], S2 = sm[e * 6 + 3];
        float S3 = sm[e * 6 + 4], S4 = sm[e * 6 + 5];
        {   // good term
            float v = a + m;
            float s = sqrt_approx(v), rv = rcp_approx(v);
            float p2 = rv * rv;
            float ser = S0 + 0.5f * S1 * rv - 0.125f * S2 * p2
                      + 0.0625f * S3 * p2 * rv - 0.0390625f * S4 * p2 * p2;
            acc += 2.0f * s * ser;
        }
        {   // bad term
            float v = cc + m;
            float s = sqrt_approx(v), rv = rcp_approx(v);
            float p2 = rv * rv;
            float ser = S0 + 0.5f * S1 * rv - 0.125f * S2 * p2
                      + 0.0625f * S3 * p2 * rv - 0.0390625f * S4 * p2 * p2;
            acc -= 1.5f * s * ser;
        }
    }

    float tot = block_sum<8>(acc);
    if (tid == 0) {
        g_jp[blockIdx.x] = tot;
        __threadfence();
        int t = atomicAdd(&g_ctr, 1);
        s_last = (t == NJB - 1);
    }
    __syncthreads();

    if (s_last) {
        double dp = 0.0, dn = 0.0;
        if (tid < NJB) dp = (double)g_jp[tid];
        for (int k = tid; k < NKB; k += 256) dn += (double)g_negp[k];
        #pragma unroll
        for (int o = 16; o > 0; o >>= 1) {
            dp += __shfl_down_sync(0xffffffffu, dp, o);
            dn += __shfl_down_sync(0xffffffffu, dn, o);
        }
        __shared__ double shp[8], shn[8];
        int lane = tid & 31, wid = tid >> 5;
        if (lane == 0) { shp[wid] = dp; shn[wid] = dn; }
        __syncthreads();
        if (tid == 0) {
            double tp = 0.0, tn = 0.0;
            #pragma unroll
            for (int w = 0; w < 8; w++) { tp += shp[w]; tn += shn[w]; }
            double mg = tp / ((double)NPAIR * (double)NPAIR);
            double l = mg + 5.25;
            if (l < 0.0) l = 0.0;
            out[0] = (float)(l + tn / (double)CELLS);
            g_ctr = 0;      // reset for next graph replay
        }
    }
}

// ---------------- launch ----------------
extern "C" void kernel_launch(void* const* d_in, const int* in_sizes, int n_in,
                              void* d_out, int out_size) {
    const float* pred = (const float*)d_in[0];   // [64,3,32,32,5]
    const float* tgt  = (const float*)d_in[1];   // [64,100,4]
    float* out = (float*)d_out;

    k_keys   <<<NKB, 256>>>(pred, tgt);
    k_select <<<BATCH, TKT>>>(pred);
    k_stats  <<<1, 256>>>();
    k_ioumax <<<dim3(NIOUB, NPAIR / PCHUNK), 128>>>();
    k_jloss  <<<NJB, 256>>>(out);
}

// round 16
// speedup vs baseline: 2.3209x; 2.3209x over previous
#include <cuda_runtime.h>
#include <cstdint>
#include <cstddef>

// Problem constants
#define BATCH   64
#define CPB     3072           // anchors*H*W per batch (3*32*32)
#define CELLS   (BATCH*CPB)    // 196608
#define KSEL    100
#define NPAIR   (BATCH*KSEL)   // 6400
#define PCHUNK  320            // preds per IoU chunk (20 chunks)
#define NIOUB   50             // iou x-blocks (128 targets each)
#define NJB     25             // jloss blocks
#define TKT     512            // select threads
#define NKB     (CELLS/256)    // 768 key-builder blocks
#define NBUK    128            // quarter-octave b-buckets over [2^-32, 1)

// ---------------- scratch (device globals; no allocation) ----------------
__device__ float4 g_p4[NPAIR];        // selected pred corners
__device__ float  g_pa[NPAIR];        // pred areas
__device__ float4 g_t4[NPAIR];        // fixed target corners
__device__ float  g_topv[NPAIR];      // selected confidences
__device__ int    g_miou[NPAIR];      // max IoU per target (float bits, >=0)
__device__ float  g_diou[NPAIR];
__device__ unsigned int g_keys[CELLS];// order-preserving conf keys
__device__ float  g_negp[NKB];        // negpen partials
__device__ float  g_sl1p[NIOUB];      // smooth-l1 partials
__device__ float  g_sl1tot;           // reduced sl1 (already scaled)
__device__ float  g_jp[NJB];          // per-block j-loss partials
__device__ float  g_bsum[NBUK*5];     // per-bucket power sums S0..S4
__device__ int    g_ctr, g_ctr2;      // last-block counters (self-resetting)

// ---------------- helpers ----------------
__device__ __forceinline__ float rcp_approx(float x) {
    float y; asm("rcp.approx.f32 %0, %1;" : "=f"(y) : "f"(x)); return y;
}
__device__ __forceinline__ float sqrt_approx(float x) {
    float y; asm("sqrt.approx.f32 %0, %1;" : "=f"(y) : "f"(x)); return y;
}
__device__ __forceinline__ float sigmoidf_(float x) {
    return 1.0f / (1.0f + expf(-x));
}

// full-block float sum, result valid in thread 0 (NW warps)
template<int NW>
__device__ __forceinline__ float block_sum(float v) {
    __shared__ float sh[NW];
    #pragma unroll
    for (int o = 16; o > 0; o >>= 1) v += __shfl_down_sync(0xffffffffu, v, o);
    int lane = threadIdx.x & 31, wid = threadIdx.x >> 5;
    if (lane == 0) sh[wid] = v;
    __syncthreads();
    float s = 0.0f;
    if (wid == 0) {
        s = (lane < NW) ? sh[lane] : 0.0f;
        #pragma unroll
        for (int o = NW / 2; o > 0; o >>= 1) s += __shfl_down_sync(0xffffffffu, s, o);
    }
    __syncthreads();   // safe smem reuse by later calls
    return s;
}

// ---------------- kernels ----------------

// Full-chip streaming pass: order-preserving conf keys + negpen partials.
// Blocks < 25 also fix targets + init miou; block 25 zeroes g_bsum.
__global__ void k_keys(const float* __restrict__ pred, const float* __restrict__ tgt) {
    __shared__ float4 buf[320];
    int blk = blockIdx.x, tid = threadIdx.x;
    const float4* src = (const float4*)pred + (size_t)blk * 320;
    #pragma unroll 2
    for (int i = tid; i < 320; i += 256) buf[i] = src[i];
    __syncthreads();
    const float* f = (const float*)buf;
    float pw = f[tid * 5 + 2], ph = f[tid * 5 + 3], cl = f[tid * 5 + 4];
    float neg = fmaxf(1.0f - pw, 0.0f) + fmaxf(1.0f - ph, 0.0f);
    unsigned int u = __float_as_uint(cl);
    u = (u & 0x80000000u) ? ~u : (u | 0x80000000u);   // order-preserving
    g_keys[blk * 256 + tid] = u;
    float tot = block_sum<8>(neg);
    if (tid == 0) g_negp[blk] = tot;

    if (blk < 25) {   // fused target fix + miou init (j < 6400)
        int j = blk * 256 + tid;
        g_miou[j] = 0;
        const float* t = tgt + (size_t)j * 4;
        float a = t[0], b = t[1], c = t[2], d = t[3];
        float x1 = fminf(a, c), x2 = fmaxf(a, c);
        float y1 = fminf(b, d), y2 = fmaxf(b, d);
        if (x1 == x2) x2 = x1 + 1.0f;
        if (y1 == y2) y2 = y1 + 1.0f;
        g_t4[j] = make_float4(x1, y1, x2, y2);
    } else if (blk == 25) {   // zero bucket sums for this replay
        for (int i = tid; i < NBUK * 5; i += 256) g_bsum[i] = 0.0f;
    }
}

// Per-batch top-100 on L2-hot keys: 12-bit radix-select + hybrid bitonic;
// exact jax ordering (ties -> smaller idx).
__global__ void __launch_bounds__(TKT) k_select(const float* __restrict__ pred) {
    __shared__ unsigned int keys[CPB];          // 12KB
    __shared__ unsigned int hist[4096];         // 16KB
    __shared__ unsigned long long cand[512];    // 4KB
    __shared__ unsigned int tsum[256];
    __shared__ unsigned int safter[256];
    __shared__ unsigned int wsum[8];
    __shared__ unsigned int s_cnt, s_pivot;

    int b = blockIdx.x;
    int tid = threadIdx.x;
    int lane = tid & 31, wid = tid >> 5;

    for (int i = tid; i < 4096; i += TKT) hist[i] = 0;
    if (tid == 0) s_cnt = 0;
    __syncthreads();

    const unsigned int* gk = g_keys + (size_t)b * CPB;
    #pragma unroll
    for (int s = tid; s < CPB; s += TKT) {
        unsigned int u = gk[s];
        keys[s] = u;
        atomicAdd(&hist[u >> 20], 1u);
    }
    __syncthreads();

    // parallel suffix scan over 4096 buckets (16/thread, 256 threads)
    unsigned int sv = 0;
    if (tid < 256) {
        unsigned int s0 = 0;
        #pragma unroll
        for (int q = 0; q < 16; q++) s0 += hist[tid * 16 + q];
        tsum[tid] = s0;
        sv = s0;
        #pragma unroll
        for (int o = 1; o < 32; o <<= 1) {
            unsigned int t = __shfl_down_sync(0xffffffffu, sv, o);
            if (lane + o < 32) sv += t;           // in-warp inclusive suffix
        }
        if (lane == 0) wsum[wid] = sv;
    }
    __syncthreads();
    if (tid < 256) {
        unsigned int hi = 0;
        #pragma unroll
        for (int w = 0; w < 8; w++) if (w > wid) hi += wsum[w];
        safter[tid] = sv + hi - tsum[tid];        // exclusive suffix
        unsigned int run = safter[tid];
        for (int q = 15; q >= 0; q--) {
            unsigned int c = hist[tid * 16 + q];
            run += c;
            if (run >= KSEL && (run - c) < KSEL) s_pivot = tid * 16 + q;
        }
    }
    __syncthreads();
    unsigned int piv = s_pivot;

    // gather candidates (buckets >= pivot)
    #pragma unroll
    for (int s = tid; s < CPB; s += TKT) {
        unsigned int u = keys[s];
        if ((u >> 20) >= piv) {
            unsigned int pos = atomicAdd(&s_cnt, 1u);
            if (pos < 512)
                cand[pos] = ((unsigned long long)u << 32) |
                            (unsigned long long)(0xFFFFFFFFu - (unsigned int)s);
        }
    }
    __syncthreads();
    unsigned int cnt = s_cnt; if (cnt > 512) cnt = 512;
    if (tid >= (int)cnt) cand[tid] = 0ull;
    __syncthreads();

    // hybrid bitonic sort (descending), 1 elem/thread
    unsigned long long v = cand[tid];
    #pragma unroll
    for (unsigned int k = 2; k <= 32; k <<= 1) {
        #pragma unroll
        for (unsigned int j = k >> 1; j > 0; j >>= 1) {
            unsigned long long t = __shfl_xor_sync(0xffffffffu, v, j);
            bool keep_max = (((tid & j) == 0) == ((tid & k) == 0));
            v = (keep_max == (v > t)) ? v : t;
        }
    }
    #pragma unroll
    for (unsigned int k = 64; k <= 512; k <<= 1) {
        for (unsigned int j = k >> 1; j >= 32; j >>= 1) {
            cand[tid] = v;
            __syncthreads();
            unsigned long long t = cand[tid ^ j];
            bool keep_max = (((tid & j) == 0) == ((tid & k) == 0));
            v = (keep_max == (v > t)) ? v : t;
            __syncthreads();
        }
        #pragma unroll
        for (unsigned int j = 16; j > 0; j >>= 1) {
            unsigned long long t = __shfl_xor_sync(0xffffffffu, v, j);
            bool keep_max = (((tid & j) == 0) == ((tid & k) == 0));
            v = (keep_max == (v > t)) ? v : t;
        }
    }
    cand[tid] = v;
    __syncthreads();

    // winners -> postprocessed pred corners
    if (tid < KSEL) {
        unsigned long long m = cand[tid];
        int idx = (int)(0xFFFFFFFFu - (unsigned int)(m & 0xFFFFFFFFull));
        int j = b * KSEL + tid;
        const float* p = pred + (size_t)b * CPB * 5 + (size_t)idx * 5;
        float x = (sigmoidf_(p[0]) + (float)(idx & 31)) * 32.0f;         // + cx, *STRIDE
        float y = (sigmoidf_(p[1]) + (float)((idx >> 5) & 31)) * 32.0f;  // + cy
        float hw = expf(p[2]) * 32.0f * 0.5f;
        float hh = expf(p[3]) * 32.0f * 0.5f;
        float x1 = x - hw, y1 = y - hh, x2 = x + hw, y2 = y + hh;
        g_p4[j] = make_float4(x1, y1, x2, y2);
        g_pa[j] = (x2 - x1) * (y2 - y1);
        g_topv[j] = sigmoidf_(p[4]);
    }
}

// max IoU over all preds per target (division-free monotone q trick).
// 1000 blocks (50 x 20). y==0 blocks also do DIoU + smooth-L1 (last one
// folds g_sl1tot). y==1 blocks also build the bucket power sums via an
// OWNER-SCAN (no atomic contention): thread t owns bucket t, scans the
// block's 128 staged (b, bucket) pairs, then a few spread gmem atomics.
__global__ void k_ioumax() {
    __shared__ float4 sp[PCHUNK];
    __shared__ float  sa[PCHUNK];
    __shared__ float  s_bv[128];
    __shared__ int    s_bk[128];
    int tid = threadIdx.x;
    int pbase = blockIdx.y * PCHUNK;
    for (int p = tid; p < PCHUNK; p += 128) {
        sp[p] = g_p4[pbase + p];
        sa[p] = g_pa[pbase + p];
    }
    __syncthreads();

    int t = blockIdx.x * 128 + tid;
    float4 T = g_t4[t];
    float ta = (T.z - T.x) * (T.w - T.y);
    float qb = 0.0f;
    #pragma unroll 4
    for (int p = 0; p < PCHUNK; p++) {
        float4 P = sp[p];            // broadcast LDS.128
        float ix1 = fmaxf(P.x, T.x);
        float iy1 = fmaxf(P.y, T.y);
        float ix2 = fminf(P.z, T.z);
        float iy2 = fminf(P.w, T.w);
        float w = fmaxf(ix2 - ix1, 0.0f);
        float h = fmaxf(iy2 - iy1, 0.0f);
        float inter = w * h;
        float s = sa[p] + ta;
        float q = inter * rcp_approx(s);
        qb = fmaxf(qb, q);
    }
    float iou = qb / (1.0f - qb);    // q in [0, 0.5] -> safe
    atomicMax(&g_miou[t], __float_as_int(iou));  // bits compare OK: iou >= 0

    if (blockIdx.y == 0) {
        float4 P = g_p4[t];
        float pa = fmaxf(P.z - P.x, 0.0f) * fmaxf(P.w - P.y, 0.0f);
        float tta = fmaxf(T.z - T.x, 0.0f) * fmaxf(T.w - T.y, 0.0f);
        float ix1 = fmaxf(P.x, T.x), iy1 = fmaxf(P.y, T.y);
        float ix2 = fminf(P.z, T.z), iy2 = fminf(P.w, T.w);
        float inter = fmaxf(ix2 - ix1, 0.0f) * fmaxf(iy2 - iy1, 0.0f);
        float iou2 = inter / (pa + tta - inter + 1e-7f);
        float dx = (P.x + P.z) * 0.5f - (T.x + T.z) * 0.5f;
        float dy = (P.y + P.w) * 0.5f - (T.y + T.w) * 0.5f;
        float cd = dx * dx + dy * dy;
        float gx = fmaxf(P.z, T.z) - fminf(P.x, T.x);
        float gy = fmaxf(P.w, T.w) - fminf(P.y, T.y);
        float diag = gx * gx + gy * gy;
        g_diou[t] = 1.0f - (iou2 - cd / (diag + 1e-7f));
        float c0 = P.x - T.x, c1 = P.y - T.y, c2 = P.z - T.z, c3 = P.w - T.w;
        float a0 = fabsf(c0), a1 = fabsf(c1), a2 = fabsf(c2), a3 = fabsf(c3);
        float sl = 0.0f;
        sl += (a0 < 1.0f) ? 0.5f * c0 * c0 : (a0 - 0.5f);
        sl += (a1 < 1.0f) ? 0.5f * c1 * c1 : (a1 - 0.5f);
        sl += (a2 < 1.0f) ? 0.5f * c2 * c2 : (a2 - 0.5f);
        sl += (a3 < 1.0f) ? 0.5f * c3 * c3 : (a3 - 0.5f);
        float tot = block_sum<4>(sl);
        if (tid == 0) {
            g_sl1p[blockIdx.x] = tot;
            __threadfence();
            int c = atomicAdd(&g_ctr2, 1);
            if (c == NIOUB - 1) {               // last sl1 block reduces
                float s = 0.0f;
                #pragma unroll 10
                for (int k2 = 0; k2 < NIOUB; k2++) s += g_sl1p[k2];
                g_sl1tot = s * (1.0f / (25600.0f * 512.0f));  // /(N*4)/DESIRED_SIZE
                g_ctr2 = 0;                     // reset for next replay
            }
        }
    } else if (blockIdx.y == 1) {
        // bucket stats for this block's 128 b-values
        float y = g_topv[t];
        float b = (1.0f - y) * (1.0f - y);
        b = fminf(fmaxf(b, 2.3283064e-10f /*2^-32*/), 0.999f);
        int k = (int)floorf(4.0f * __log2f(b)) + 128;
        k = max(0, min(NBUK - 1, k));
        s_bv[tid] = b;
        s_bk[tid] = k;
        __syncthreads();
        // owner scan: thread tid owns bucket tid
        float m = exp2f(0.25f * ((float)tid + 0.5f) - 32.0f);
        float S0 = 0, S1 = 0, S2 = 0, S3 = 0, S4 = 0;
        for (int v = 0; v < 128; v++) {
            if (s_bk[v] == tid) {
                float tt = s_bv[v] - m;
                float t2 = tt * tt;
                S0 += 1.0f; S1 += tt; S2 += t2; S3 += t2 * tt; S4 += t2 * t2;
            }
        }
        if (S0 > 0.0f) {
            atomicAdd(&g_bsum[tid * 5 + 0], S0);
            atomicAdd(&g_bsum[tid * 5 + 1], S1);
            atomicAdd(&g_bsum[tid * 5 + 2], S2);
            atomicAdd(&g_bsum[tid * 5 + 3], S3);
            atomicAdd(&g_bsum[tid * 5 + 4], S4);
        }
    }
}

// Per-j bucketed series: for each occupied b-bucket, order-4 expansion of
// sum_i sqrt(v + t_i) around v = {a,c} + m_k. |t|/(c+m) <= ~0.0905 by
// construction -> always convergent, no guard, no fallback.
__global__ void __launch_bounds__(256) k_jloss(float* __restrict__ out) {
    __shared__ float sb[NBUK * 5];
    __shared__ bool  s_last;
    int tid = threadIdx.x;
    for (int i = tid; i < NBUK * 5; i += 256) sb[i] = g_bsum[i];
    __syncthreads();

    float sl1 = g_sl1tot;
    int j = blockIdx.x * 256 + tid;
    float mi = fmaxf(__int_as_float(g_miou[j]), 0.0f);
    float x = 2.0f * (1.0f - mi) + g_diou[j] + sl1;
    float a = x * x;
    float xm = 3.5f - x;
    float cc = xm * xm;

    float acc = 0.0f;
    for (int k = 0; k < NBUK; k++) {
        float S0 = sb[k * 5];
        if (S0 != 0.0f) {                 // uniform branch (smem broadcast)
            float m = exp2f(0.25f * ((float)k + 0.5f) - 32.0f);
            float S1 = sb[k * 5 + 1], S2 = sb[k * 5 + 2];
            float S3 = sb[k * 5 + 3], S4 = sb[k * 5 + 4];
            {   // good term
                float v = a + m;
                float s = sqrt_approx(v), rv = rcp_approx(v);
                float p2 = rv * rv;
                float ser = S0 + 0.5f * S1 * rv - 0.125f * S2 * p2
                          + 0.0625f * S3 * p2 * rv - 0.0390625f * S4 * p2 * p2;
                acc += 2.0f * s * ser;
            }
            {   // bad term
                float v = cc + m;
                float s = sqrt_approx(v), rv = rcp_approx(v);
                float p2 = rv * rv;
                float ser = S0 + 0.5f * S1 * rv - 0.125f * S2 * p2
                          + 0.0625f * S3 * p2 * rv - 0.0390625f * S4 * p2 * p2;
                acc -= 1.5f * s * ser;
            }
        }
    }

    float tot = block_sum<8>(acc);
    if (tid == 0) {
        g_jp[blockIdx.x] = tot;
        __threadfence();
        int t = atomicAdd(&g_ctr, 1);
        s_last = (t == NJB - 1);
    }
    __syncthreads();

    if (s_last) {
        double dp = 0.0, dn = 0.0;
        if (tid < NJB) dp = (double)g_jp[tid];
        for (int k = tid; k < NKB; k += 256) dn += (double)g_negp[k];
        #pragma unroll
        for (int o = 16; o > 0; o >>= 1) {
            dp += __shfl_down_sync(0xffffffffu, dp, o);
            dn += __shfl_down_sync(0xffffffffu, dn, o);
        }
        __shared__ double shp[8], shn[8];
        int lane = tid & 31, wid = tid >> 5;
        if (lane == 0) { shp[wid] = dp; shn[wid] = dn; }
        __syncthreads();
        if (tid == 0) {
            double tp = 0.0, tn = 0.0;
            #pragma unroll
            for (int w = 0; w < 8; w++) { tp += shp[w]; tn += shn[w]; }
            double mg = tp / ((double)NPAIR * (double)NPAIR);
            double l = mg + 5.25;
            if (l < 0.0) l = 0.0;
            out[0] = (float)(l + tn / (double)CELLS);
            g_ctr = 0;      // reset for next graph replay
        }
    }
}

// ---------------- launch ----------------
extern "C" void kernel_launch(void* const* d_in, const int* in_sizes, int n_in,
                              void* d_out, int out_size) {
    const float* pred = (const float*)d_in[0];   // [64,3,32,32,5]
    const float* tgt  = (const float*)d_in[1];   // [64,100,4]
    float* out = (float*)d_out;

    k_keys   <<<NKB, 256>>>(pred, tgt);
    k_select <<<BATCH, TKT>>>(pred);
    k_ioumax <<<dim3(NIOUB, NPAIR / PCHUNK), 128>>>();
    k_jloss  <<<NJB, 256>>>(out);
}

// round 17
// speedup vs baseline: 2.4121x; 1.0393x over previous
#include <cuda_runtime.h>
#include <cstdint>
#include <cstddef>

// Problem constants
#define BATCH   64
#define CPB     3072           // anchors*H*W per batch (3*32*32)
#define CELLS   (BATCH*CPB)    // 196608
#define KSEL    100
#define NPAIR   (BATCH*KSEL)   // 6400
#define PCHUNK  320            // preds per IoU chunk (20 chunks)
#define NIOUB   50             // iou x-blocks (128 targets each)
#define NJB     100            // jloss blocks (64 j each, 4 threads/j)
#define TKT     512            // select threads
#define NKB     (CELLS/256)    // 768 key-builder blocks
#define NBUK    128            // quarter-octave b-buckets over [2^-32, 1)

// ---------------- scratch (device globals; no allocation) ----------------
__device__ float4 g_p4[NPAIR];        // selected pred corners
__device__ float  g_pa[NPAIR];        // pred areas
__device__ float4 g_t4[NPAIR];        // fixed target corners
__device__ float  g_topv[NPAIR];      // selected confidences
__device__ int    g_miou[NPAIR];      // max IoU per target (float bits, >=0)
__device__ float  g_diou[NPAIR];
__device__ unsigned int g_keys[CELLS];// order-preserving conf keys
__device__ float  g_negp[NKB];        // negpen partials
__device__ float  g_sl1p[NIOUB];      // smooth-l1 partials
__device__ float  g_sl1tot;           // reduced sl1 (already scaled)
__device__ float  g_jp[NJB];          // per-block j-loss partials
__device__ float  g_bsum[NBUK*5];     // per-bucket power sums S0..S4
__device__ int    g_ctr, g_ctr2;      // last-block counters (self-resetting)

// ---------------- helpers ----------------
__device__ __forceinline__ float rcp_approx(float x) {
    float y; asm("rcp.approx.f32 %0, %1;" : "=f"(y) : "f"(x)); return y;
}
__device__ __forceinline__ float sqrt_approx(float x) {
    float y; asm("sqrt.approx.f32 %0, %1;" : "=f"(y) : "f"(x)); return y;
}
__device__ __forceinline__ float sigmoidf_(float x) {
    return 1.0f / (1.0f + expf(-x));
}

// full-block float sum, result valid in thread 0 (NW warps)
template<int NW>
__device__ __forceinline__ float block_sum(float v) {
    __shared__ float sh[NW];
    #pragma unroll
    for (int o = 16; o > 0; o >>= 1) v += __shfl_down_sync(0xffffffffu, v, o);
    int lane = threadIdx.x & 31, wid = threadIdx.x >> 5;
    if (lane == 0) sh[wid] = v;
    __syncthreads();
    float s = 0.0f;
    if (wid == 0) {
        s = (lane < NW) ? sh[lane] : 0.0f;
        #pragma unroll
        for (int o = NW / 2; o > 0; o >>= 1) s += __shfl_down_sync(0xffffffffu, s, o);
    }
    __syncthreads();   // safe smem reuse by later calls
    return s;
}

// ---------------- kernels ----------------

// Full-chip streaming pass: order-preserving conf keys + negpen partials.
// Blocks < 25 also fix targets + init miou; block 25 zeroes g_bsum.
__global__ void k_keys(const float* __restrict__ pred, const float* __restrict__ tgt) {
    __shared__ float4 buf[320];
    int blk = blockIdx.x, tid = threadIdx.x;
    const float4* src = (const float4*)pred + (size_t)blk * 320;
    #pragma unroll 2
    for (int i = tid; i < 320; i += 256) buf[i] = src[i];
    __syncthreads();
    const float* f = (const float*)buf;
    float pw = f[tid * 5 + 2], ph = f[tid * 5 + 3], cl = f[tid * 5 + 4];
    float neg = fmaxf(1.0f - pw, 0.0f) + fmaxf(1.0f - ph, 0.0f);
    unsigned int u = __float_as_uint(cl);
    u = (u & 0x80000000u) ? ~u : (u | 0x80000000u);   // order-preserving
    g_keys[blk * 256 + tid] = u;
    float tot = block_sum<8>(neg);
    if (tid == 0) g_negp[blk] = tot;

    if (blk < 25) {   // fused target fix + miou init (j < 6400)
        int j = blk * 256 + tid;
        g_miou[j] = 0;
        const float* t = tgt + (size_t)j * 4;
        float a = t[0], b = t[1], c = t[2], d = t[3];
        float x1 = fminf(a, c), x2 = fmaxf(a, c);
        float y1 = fminf(b, d), y2 = fmaxf(b, d);
        if (x1 == x2) x2 = x1 + 1.0f;
        if (y1 == y2) y2 = y1 + 1.0f;
        g_t4[j] = make_float4(x1, y1, x2, y2);
    } else if (blk == 25) {   // zero bucket sums for this replay
        for (int i = tid; i < NBUK * 5; i += 256) g_bsum[i] = 0.0f;
    }
}

// Per-batch top-100 on L2-hot keys: 12-bit radix-select + hybrid bitonic;
// exact jax ordering (ties -> smaller idx).
__global__ void __launch_bounds__(TKT) k_select(const float* __restrict__ pred) {
    __shared__ unsigned int keys[CPB];          // 12KB
    __shared__ unsigned int hist[4096];         // 16KB
    __shared__ unsigned long long cand[512];    // 4KB
    __shared__ unsigned int tsum[256];
    __shared__ unsigned int safter[256];
    __shared__ unsigned int wsum[8];
    __shared__ unsigned int s_cnt, s_pivot;

    int b = blockIdx.x;
    int tid = threadIdx.x;
    int lane = tid & 31, wid = tid >> 5;

    for (int i = tid; i < 4096; i += TKT) hist[i] = 0;
    if (tid == 0) s_cnt = 0;
    __syncthreads();

    const unsigned int* gk = g_keys + (size_t)b * CPB;
    #pragma unroll
    for (int s = tid; s < CPB; s += TKT) {
        unsigned int u = gk[s];
        keys[s] = u;
        atomicAdd(&hist[u >> 20], 1u);
    }
    __syncthreads();

    // parallel suffix scan over 4096 buckets (16/thread, 256 threads)
    unsigned int sv = 0;
    if (tid < 256) {
        unsigned int s0 = 0;
        #pragma unroll
        for (int q = 0; q < 16; q++) s0 += hist[tid * 16 + q];
        tsum[tid] = s0;
        sv = s0;
        #pragma unroll
        for (int o = 1; o < 32; o <<= 1) {
            unsigned int t = __shfl_down_sync(0xffffffffu, sv, o);
            if (lane + o < 32) sv += t;           // in-warp inclusive suffix
        }
        if (lane == 0) wsum[wid] = sv;
    }
    __syncthreads();
    if (tid < 256) {
        unsigned int hi = 0;
        #pragma unroll
        for (int w = 0; w < 8; w++) if (w > wid) hi += wsum[w];
        safter[tid] = sv + hi - tsum[tid];        // exclusive suffix
        unsigned int run = safter[tid];
        for (int q = 15; q >= 0; q--) {
            unsigned int c = hist[tid * 16 + q];
            run += c;
            if (run >= KSEL && (run - c) < KSEL) s_pivot = tid * 16 + q;
        }
    }
    __syncthreads();
    unsigned int piv = s_pivot;

    // gather candidates (buckets >= pivot)
    #pragma unroll
    for (int s = tid; s < CPB; s += TKT) {
        unsigned int u = keys[s];
        if ((u >> 20) >= piv) {
            unsigned int pos = atomicAdd(&s_cnt, 1u);
            if (pos < 512)
                cand[pos] = ((unsigned long long)u << 32) |
                            (unsigned long long)(0xFFFFFFFFu - (unsigned int)s);
        }
    }
    __syncthreads();
    unsigned int cnt = s_cnt; if (cnt > 512) cnt = 512;
    if (tid >= (int)cnt) cand[tid] = 0ull;
    __syncthreads();

    // hybrid bitonic sort (descending), 1 elem/thread
    unsigned long long v = cand[tid];
    #pragma unroll
    for (unsigned int k = 2; k <= 32; k <<= 1) {
        #pragma unroll
        for (unsigned int j = k >> 1; j > 0; j >>= 1) {
            unsigned long long t = __shfl_xor_sync(0xffffffffu, v, j);
            bool keep_max = (((tid & j) == 0) == ((tid & k) == 0));
            v = (keep_max == (v > t)) ? v : t;
        }
    }
    #pragma unroll
    for (unsigned int k = 64; k <= 512; k <<= 1) {
        for (unsigned int j = k >> 1; j >= 32; j >>= 1) {
            cand[tid] = v;
            __syncthreads();
            unsigned long long t = cand[tid ^ j];
            bool keep_max = (((tid & j) == 0) == ((tid & k) == 0));
            v = (keep_max == (v > t)) ? v : t;
            __syncthreads();
        }
        #pragma unroll
        for (unsigned int j = 16; j > 0; j >>= 1) {
            unsigned long long t = __shfl_xor_sync(0xffffffffu, v, j);
            bool keep_max = (((tid & j) == 0) == ((tid & k) == 0));
            v = (keep_max == (v > t)) ? v : t;
        }
    }
    cand[tid] = v;
    __syncthreads();

    // winners -> postprocessed pred corners
    if (tid < KSEL) {
        unsigned long long m = cand[tid];
        int idx = (int)(0xFFFFFFFFu - (unsigned int)(m & 0xFFFFFFFFull));
        int j = b * KSEL + tid;
        const float* p = pred + (size_t)b * CPB * 5 + (size_t)idx * 5;
        float x = (sigmoidf_(p[0]) + (float)(idx & 31)) * 32.0f;         // + cx, *STRIDE
        float y = (sigmoidf_(p[1]) + (float)((idx >> 5) & 31)) * 32.0f;  // + cy
        float hw = expf(p[2]) * 32.0f * 0.5f;
        float hh = expf(p[3]) * 32.0f * 0.5f;
        float x1 = x - hw, y1 = y - hh, x2 = x + hw, y2 = y + hh;
        g_p4[j] = make_float4(x1, y1, x2, y2);
        g_pa[j] = (x2 - x1) * (y2 - y1);
        g_topv[j] = sigmoidf_(p[4]);
    }
}

// max IoU over all preds per target (division-free monotone q trick).
// 1000 blocks (50 x 20). y==0 blocks also do DIoU + smooth-L1 (last one
// folds g_sl1tot). y==1 blocks also build the bucket power sums via an
// OWNER-SCAN (no atomic contention): thread t owns bucket t, scans the
// block's 128 staged (b, bucket) pairs, then a few spread gmem atomics.
__global__ void k_ioumax() {
    __shared__ float4 sp[PCHUNK];
    __shared__ float  sa[PCHUNK];
    __shared__ float  s_bv[128];
    __shared__ int    s_bk[128];
    int tid = threadIdx.x;
    int pbase = blockIdx.y * PCHUNK;
    for (int p = tid; p < PCHUNK; p += 128) {
        sp[p] = g_p4[pbase + p];
        sa[p] = g_pa[pbase + p];
    }
    __syncthreads();

    int t = blockIdx.x * 128 + tid;
    float4 T = g_t4[t];
    float ta = (T.z - T.x) * (T.w - T.y);
    float qb = 0.0f;
    #pragma unroll 4
    for (int p = 0; p < PCHUNK; p++) {
        float4 P = sp[p];            // broadcast LDS.128
        float ix1 = fmaxf(P.x, T.x);
        float iy1 = fmaxf(P.y, T.y);
        float ix2 = fminf(P.z, T.z);
        float iy2 = fminf(P.w, T.w);
        float w = fmaxf(ix2 - ix1, 0.0f);
        float h = fmaxf(iy2 - iy1, 0.0f);
        float inter = w * h;
        float s = sa[p] + ta;
        float q = inter * rcp_approx(s);
        qb = fmaxf(qb, q);
    }
    float iou = qb / (1.0f - qb);    // q in [0, 0.5] -> safe
    atomicMax(&g_miou[t], __float_as_int(iou));  // bits compare OK: iou >= 0

    if (blockIdx.y == 0) {
        float4 P = g_p4[t];
        float pa = fmaxf(P.z - P.x, 0.0f) * fmaxf(P.w - P.y, 0.0f);
        float tta = fmaxf(T.z - T.x, 0.0f) * fmaxf(T.w - T.y, 0.0f);
        float ix1 = fmaxf(P.x, T.x), iy1 = fmaxf(P.y, T.y);
        float ix2 = fminf(P.z, T.z), iy2 = fminf(P.w, T.w);
        float inter = fmaxf(ix2 - ix1, 0.0f) * fmaxf(iy2 - iy1, 0.0f);
        float iou2 = inter / (pa + tta - inter + 1e-7f);
        float dx = (P.x + P.z) * 0.5f - (T.x + T.z) * 0.5f;
        float dy = (P.y + P.w) * 0.5f - (T.y + T.w) * 0.5f;
        float cd = dx * dx + dy * dy;
        float gx = fmaxf(P.z, T.z) - fminf(P.x, T.x);
        float gy = fmaxf(P.w, T.w) - fminf(P.y, T.y);
        float diag = gx * gx + gy * gy;
        g_diou[t] = 1.0f - (iou2 - cd / (diag + 1e-7f));
        float c0 = P.x - T.x, c1 = P.y - T.y, c2 = P.z - T.z, c3 = P.w - T.w;
        float a0 = fabsf(c0), a1 = fabsf(c1), a2 = fabsf(c2), a3 = fabsf(c3);
        float sl = 0.0f;
        sl += (a0 < 1.0f) ? 0.5f * c0 * c0 : (a0 - 0.5f);
        sl += (a1 < 1.0f) ? 0.5f * c1 * c1 : (a1 - 0.5f);
        sl += (a2 < 1.0f) ? 0.5f * c2 * c2 : (a2 - 0.5f);
        sl += (a3 < 1.0f) ? 0.5f * c3 * c3 : (a3 - 0.5f);
        float tot = block_sum<4>(sl);
        if (tid == 0) {
            g_sl1p[blockIdx.x] = tot;
            __threadfence();
            int c = atomicAdd(&g_ctr2, 1);
            if (c == NIOUB - 1) {               // last sl1 block reduces
                float s = 0.0f;
                #pragma unroll 10
                for (int k2 = 0; k2 < NIOUB; k2++) s += g_sl1p[k2];
                g_sl1tot = s * (1.0f / (25600.0f * 512.0f));  // /(N*4)/DESIRED_SIZE
                g_ctr2 = 0;                     // reset for next replay
            }
        }
    } else if (blockIdx.y == 1) {
        // bucket stats for this block's 128 b-values
        float y = g_topv[t];
        float b = (1.0f - y) * (1.0f - y);
        b = fminf(fmaxf(b, 2.3283064e-10f /*2^-32*/), 0.999f);
        int k = (int)floorf(4.0f * __log2f(b)) + 128;
        k = max(0, min(NBUK - 1, k));
        s_bv[tid] = b;
        s_bk[tid] = k;
        __syncthreads();
        // owner scan: thread tid owns bucket tid
        float m = exp2f(0.25f * ((float)tid + 0.5f) - 32.0f);
        float S0 = 0, S1 = 0, S2 = 0, S3 = 0, S4 = 0;
        for (int v = 0; v < 128; v++) {
            if (s_bk[v] == tid) {
                float tt = s_bv[v] - m;
                float t2 = tt * tt;
                S0 += 1.0f; S1 += tt; S2 += t2; S3 += t2 * tt; S4 += t2 * t2;
            }
        }
        if (S0 > 0.0f) {
            atomicAdd(&g_bsum[tid * 5 + 0], S0);
            atomicAdd(&g_bsum[tid * 5 + 1], S1);
            atomicAdd(&g_bsum[tid * 5 + 2], S2);
            atomicAdd(&g_bsum[tid * 5 + 3], S3);
            atomicAdd(&g_bsum[tid * 5 + 4], S4);
        }
    }
}

// Per-j bucketed series, 4 threads per j (each owns 32 of 128 buckets).
// 100 blocks x 256 threads = 64 j per block. Only the global sum matters,
// so per-thread partials fold straight into the block sum.
__global__ void __launch_bounds__(256) k_jloss(float* __restrict__ out) {
    __shared__ float sb[NBUK * 5];
    __shared__ bool  s_last;
    int tid = threadIdx.x;
    for (int i = tid; i < NBUK * 5; i += 256) sb[i] = g_bsum[i];
    __syncthreads();

    float sl1 = g_sl1tot;
    int j = blockIdx.x * 64 + (tid >> 2);
    int sub = tid & 3;
    float mi = fmaxf(__int_as_float(g_miou[j]), 0.0f);
    float x = 2.0f * (1.0f - mi) + g_diou[j] + sl1;
    float a = x * x;
    float xm = 3.5f - x;
    float cc = xm * xm;

    float acc = 0.0f;
    int k0 = sub * 32;
    for (int k = k0; k < k0 + 32; k++) {
        float S0 = sb[k * 5];
        if (S0 != 0.0f) {
            float m = exp2f(0.25f * ((float)k + 0.5f) - 32.0f);
            float S1 = sb[k * 5 + 1], S2 = sb[k * 5 + 2];
            float S3 = sb[k * 5 + 3], S4 = sb[k * 5 + 4];
            {   // good term
                float v = a + m;
                float s = sqrt_approx(v), rv = rcp_approx(v);
                float p2 = rv * rv;
                float ser = S0 + 0.5f * S1 * rv - 0.125f * S2 * p2
                          + 0.0625f * S3 * p2 * rv - 0.0390625f * S4 * p2 * p2;
                acc += 2.0f * s * ser;
            }
            {   // bad term
                float v = cc + m;
                float s = sqrt_approx(v), rv = rcp_approx(v);
                float p2 = rv * rv;
                float ser = S0 + 0.5f * S1 * rv - 0.125f * S2 * p2
                          + 0.0625f * S3 * p2 * rv - 0.0390625f * S4 * p2 * p2;
                acc -= 1.5f * s * ser;
            }
        }
    }

    float tot = block_sum<8>(acc);
    if (tid == 0) {
        g_jp[blockIdx.x] = tot;
        __threadfence();
        int t = atomicAdd(&g_ctr, 1);
        s_last = (t == NJB - 1);
    }
    __syncthreads();

    if (s_last) {
        double dp = 0.0, dn = 0.0;
        if (tid < NJB) dp = (double)g_jp[tid];
        for (int k = tid; k < NKB; k += 256) dn += (double)g_negp[k];
        #pragma unroll
        for (int o = 16; o > 0; o >>= 1) {
            dp += __shfl_down_sync(0xffffffffu, dp, o);
            dn += __shfl_down_sync(0xffffffffu, dn, o);
        }
        __shared__ double shp[8], shn[8];
        int lane = tid & 31, wid = tid >> 5;
        if (lane == 0) { shp[wid] = dp; shn[wid] = dn; }
        __syncthreads();
        if (tid == 0) {
            double tp = 0.0, tn = 0.0;
            #pragma unroll
            for (int w = 0; w < 8; w++) { tp += shp[w]; tn += shn[w]; }
            double mg = tp / ((double)NPAIR * (double)NPAIR);
            double l = mg + 5.25;
            if (l < 0.0) l = 0.0;
            out[0] = (float)(l + tn / (double)CELLS);
            g_ctr = 0;      // reset for next graph replay
        }
    }
}

// ---------------- launch ----------------
extern "C" void kernel_launch(void* const* d_in, const int* in_sizes, int n_in,
                              void* d_out, int out_size) {
    const float* pred = (const float*)d_in[0];   // [64,3,32,32,5]
    const float* tgt  = (const float*)d_in[1];   // [64,100,4]
    float* out = (float*)d_out;

    k_keys   <<<NKB, 256>>>(pred, tgt);
    k_select <<<BATCH, TKT>>>(pred);
    k_ioumax <<<dim3(NIOUB, NPAIR / PCHUNK), 128>>>();
    k_jloss  <<<NJB, 256>>>(out);
}